// round 8
// baseline (speedup 1.0000x reference)
#include <cuda_runtime.h>
#include <cuda_fp16.h>
#include <cstdint>

#define MAXC 10016
#define EMB 32
#define NB 33   // buckets = 32 knees + 1

// Scratch (__device__ globals; no allocation allowed)
__device__ __align__(16) float2 d_hist[MAXC * NB];    // per (candidate,bucket): {sum a, count}
__device__ __align__(16) float d_G[MAXC * EMB];       // pre-activation bias per candidate
__device__ float d_p[EMB], d_q[EMB], d_p1[EMB];
__device__ float d_u[EMB];
__device__ __align__(16) float d_W[EMB * EMB];        // w_t2 @ w_u1_bot
__device__ float d_q1v[EMB];
__device__ float d_ts[64];                             // sorted global thresholds (+INF pad)
__device__ int   d_perm[EMB];
// Piecewise-linear output table: out = U + a*V per (candidate, bucket)
__device__ __align__(16) float  d_Uf[(size_t)MAXC * NB * EMB];   // 42.3 MB f32
__device__ __align__(16) __half d_Vh[(size_t)MAXC * NB * EMB];   // 21.1 MB fp16
__device__ __align__(16) __half d_kneeh[MAXC * EMB];             // fp16 knees

// ---------------------------------------------------------------------------
// Precompute folded weights + sorted global thresholds (tiny, 1 block)
// ---------------------------------------------------------------------------
__global__ void precompute_kernel(const float* __restrict__ w_v2h,
                                  const float* __restrict__ b_v2h,
                                  const float* __restrict__ w_t1,
                                  const float* __restrict__ b_t1,
                                  const float* __restrict__ w_t2,
                                  const float* __restrict__ b_t2,
                                  const float* __restrict__ w_u1,
                                  const float* __restrict__ b_u1)
{
    __shared__ float tarr[EMB];
    int tid = threadIdx.x;
    int m = tid >> 5, k = tid & 31;

    float w = 0.f;
    #pragma unroll
    for (int j = 0; j < EMB; j++)
        w += w_t2[m * EMB + j] * w_u1[(EMB + j) * EMB + k];
    d_W[m * EMB + k] = w;

    if (m == 0) {
        float u = 0.f;
        #pragma unroll
        for (int j = 0; j < EMB; j++)
            u += b_t2[j] * w_u1[(EMB + j) * EMB + k];
        d_u[k] = u;

        float p = 0.f, q = 0.f, p1 = 0.f, q1 = 0.f;
        #pragma unroll
        for (int i = 0; i < EMB; i++) {
            float v = w_v2h[i];
            float b = b_v2h[i];
            p  += v * w_t1[i * EMB + k];
            q  += b * w_t1[i * EMB + k];
            p1 += v * w_u1[i * EMB + k];
            q1 += b * w_u1[i * EMB + k];
        }
        float qe = q + b_t1[k];
        d_p[k]   = p;
        d_q[k]   = qe;
        d_p1[k]  = p1;
        d_q1v[k] = q1 + b_u1[k];
        float t = (p != 0.f) ? (-qe / p) : __int_as_float(0x7f800000);
        tarr[k] = t;
    }
    __syncthreads();

    if (tid < 32) {
        float t = tarr[tid];
        int r = 0;
        #pragma unroll
        for (int j = 0; j < 32; j++) {
            float tj = tarr[j];
            r += (tj < t) || (tj == t && j < tid);
        }
        d_ts[r] = t;
        d_perm[r] = tid;
    } else if (tid < 64) {
        d_ts[tid] = __int_as_float(0x7f800000);
    }
}

// ---------------------------------------------------------------------------
// Pass 1: per-edge bucket(a) via binary search, one red.v2 {a,1} per edge
// ---------------------------------------------------------------------------
__global__ __launch_bounds__(256) void pass1_kernel(
    const float* __restrict__ edge_attr,
    const int* __restrict__ src,
    int E)
{
    __shared__ float ts[64];
    if (threadIdx.x < 64) ts[threadIdx.x] = d_ts[threadIdx.x];
    __syncthreads();

    int e = blockIdx.x * blockDim.x + threadIdx.x;
    if (e >= E) return;

    float a = edge_attr[e];
    int c = src[e];

    int pos = 0;
    #pragma unroll
    for (int s = 32; s >= 1; s >>= 1)
        if (ts[pos + s - 1] < a) pos += s;

    float2* addr = d_hist + c * NB + pos;
    asm volatile("red.global.add.v2.f32 [%0], {%1, %2};"
                 :: "l"(addr), "f"(a), "f"(1.0f) : "memory");
}

// ---------------------------------------------------------------------------
// G table: warp per candidate. Shfl-scan buckets -> sumR -> matvec with W.
// ---------------------------------------------------------------------------
__global__ __launch_bounds__(256) void gtable_kernel(int C)
{
    __shared__ float sW[EMB * EMB];
    __shared__ float su[EMB], sq1[EMB], sp[EMB], sq[EMB];
    __shared__ int sperm[EMB];
    __shared__ float sR[8][EMB];

    for (int i = threadIdx.x; i < EMB * EMB; i += blockDim.x) sW[i] = d_W[i];
    if (threadIdx.x < EMB) {
        su[threadIdx.x]  = d_u[threadIdx.x];
        sq1[threadIdx.x] = d_q1v[threadIdx.x];
        sp[threadIdx.x]  = d_p[threadIdx.x];
        sq[threadIdx.x]  = d_q[threadIdx.x];
        sperm[threadIdx.x] = d_perm[threadIdx.x];
    }
    __syncthreads();

    int lane = threadIdx.x & 31;
    int wid  = threadIdx.x >> 5;
    int c = blockIdx.x * 8 + wid;
    if (c >= C) return;

    float2 h   = d_hist[c * NB + lane];
    float2 h32 = d_hist[c * NB + 32];

    float Ps = h.x, Pn = h.y;
    #pragma unroll
    for (int d = 1; d < 32; d <<= 1) {
        float xs = __shfl_up_sync(0xffffffffu, Ps, d);
        float xn = __shfl_up_sync(0xffffffffu, Pn, d);
        if (lane >= d) { Ps += xs; Pn += xn; }
    }
    float Ts = __shfl_sync(0xffffffffu, Ps, 31) + h32.x;
    float Tn = __shfl_sync(0xffffffffu, Pn, 31) + h32.y;

    int k = sperm[lane];
    float p = sp[k], q = sq[k];
    float sumR;
    if (p > 0.f)      sumR = p * (Ts - Ps) + q * (Tn - Pn);
    else if (p < 0.f) sumR = p * Ps + q * Pn;
    else              sumR = Tn * fmaxf(q, 0.f);
    sR[wid][k] = sumR;
    __syncwarp();

    float acc = sq1[lane] + Tn * su[lane];
    #pragma unroll
    for (int m = 0; m < EMB; m++)
        acc = fmaf(sR[wid][m], sW[m * EMB + lane], acc);
    d_G[c * EMB + lane] = acc;
}

// ---------------------------------------------------------------------------
// UV build: warp per candidate. out(a) = U + a*V piecewise-linear in a.
// Knees t_j = -G[c,j]/p1_j (stored fp16); crossing knee rank b-1 toggles
// one feature. b_u2 folded into U. U stored f32, V stored fp16.
// ---------------------------------------------------------------------------
__global__ __launch_bounds__(256) void uvbuild_kernel(
    const float* __restrict__ w_u2,
    const float* __restrict__ b_u2,
    int C)
{
    __shared__ float sw2[EMB * EMB];     // w_u2[j][k]
    __shared__ float sp1[EMB], sb[EMB];
    __shared__ float st[8][EMB];         // knees per warp (f32, for exact ranking)
    __shared__ float sG[8][EMB];
    __shared__ int   sjb[8][EMB];        // rank -> feature

    for (int i = threadIdx.x; i < EMB * EMB; i += blockDim.x) sw2[i] = w_u2[i];
    if (threadIdx.x < EMB) {
        sp1[threadIdx.x] = d_p1[threadIdx.x];
        sb[threadIdx.x]  = b_u2[threadIdx.x];
    }
    __syncthreads();

    int lane = threadIdx.x & 31;
    int wid  = threadIdx.x >> 5;
    int c = blockIdx.x * 8 + wid;
    if (c >= C) return;

    float Gk  = d_G[c * EMB + lane];
    float p1k = sp1[lane];
    float t = (p1k != 0.f) ? (-Gk / p1k) : __int_as_float(0x7f800000);
    d_kneeh[c * EMB + lane] = __float2half_rn(t);   // overflow -> +-inf, OK

    st[wid][lane] = t;
    sG[wid][lane] = Gk;
    __syncwarp();

    int r = 0;
    #pragma unroll
    for (int j = 0; j < EMB; j++) {
        float tj = st[wid][j];
        r += (tj < t) || (tj == t && j < lane);
    }
    sjb[wid][r] = lane;
    __syncwarp();

    // base: bucket 0 (a below all knees): active iff p1<0, or p1==0 && G>0
    float U = sb[lane];
    float V = 0.f;
    #pragma unroll
    for (int j = 0; j < EMB; j++) {
        float pj = sp1[j];
        float gj = sG[wid][j];
        bool act = (pj < 0.f) || (pj == 0.f && gj > 0.f);
        if (act) {
            U = fmaf(gj, sw2[j * EMB + lane], U);
            V = fmaf(pj, sw2[j * EMB + lane], V);
        }
    }

    float*  urow = d_Uf + (size_t)c * NB * EMB;
    __half* vrow = d_Vh + (size_t)c * NB * EMB;
    urow[lane] = U;
    vrow[lane] = __float2half_rn(V);

    for (int b = 1; b < NB; b++) {
        int j = sjb[wid][b - 1];
        float pj = sp1[j];
        float s = (pj > 0.f) ? 1.f : ((pj < 0.f) ? -1.f : 0.f);
        float wjk = sw2[j * EMB + lane];
        U = fmaf(s * sG[wid][j], wjk, U);
        V = fmaf(s * pj, wjk, V);
        urow[b * EMB + lane] = U;
        vrow[b * EMB + lane] = __float2half_rn(V);
    }
}

// ---------------------------------------------------------------------------
// Pass 2: warp handles 8 edges/iter. Per edge: fp16 knee row (64B) ->
// ballot -> bucket; U row f32 (128B) + V row fp16 (64B); out = fma(a,V,U);
// streaming store.
// ---------------------------------------------------------------------------
__global__ __launch_bounds__(256) void pass2_kernel(
    const float* __restrict__ edge_attr,
    const int* __restrict__ src,
    float* __restrict__ out,
    int E)
{
    int lane = threadIdx.x & 31;
    int wid  = threadIdx.x >> 5;
    int gw   = blockIdx.x * 8 + wid;
    int nw   = gridDim.x * 8;

    int ngroups = (E + 7) >> 3;
    for (int g = gw; g < ngroups; g += nw) {
        int e0 = g * 8;
        float av[8];
        int   cv[8];
        bool full = (e0 + 8 <= E);
        if (full) {
            float4 aA = *(const float4*)(edge_attr + e0);
            float4 aB = *(const float4*)(edge_attr + e0 + 4);
            int4   cA = *(const int4*)(src + e0);
            int4   cB = *(const int4*)(src + e0 + 4);
            av[0]=aA.x; av[1]=aA.y; av[2]=aA.z; av[3]=aA.w;
            av[4]=aB.x; av[5]=aB.y; av[6]=aB.z; av[7]=aB.w;
            cv[0]=cA.x; cv[1]=cA.y; cv[2]=cA.z; cv[3]=cA.w;
            cv[4]=cB.x; cv[5]=cB.y; cv[6]=cB.z; cv[7]=cB.w;
        } else {
            #pragma unroll
            for (int i = 0; i < 8; i++) {
                int e = (e0 + i < E) ? (e0 + i) : (E - 1);
                av[i] = edge_attr[e];
                cv[i] = src[e];
            }
        }

        // fp16 knee rows (coalesced 64B each), MLP=8
        float tk[8];
        #pragma unroll
        for (int i = 0; i < 8; i++)
            tk[i] = __half2float(d_kneeh[cv[i] * EMB + lane]);

        int bk[8];
        #pragma unroll
        for (int i = 0; i < 8; i++)
            bk[i] = __popc(__ballot_sync(0xffffffffu, tk[i] < av[i]));

        // U rows f32 (128B) + V rows fp16 (64B), MLP=8 each
        float uf[8];
        float vf[8];
        #pragma unroll
        for (int i = 0; i < 8; i++) {
            size_t ridx = ((size_t)cv[i] * NB + bk[i]) * EMB + lane;
            uf[i] = d_Uf[ridx];
            vf[i] = __half2float(d_Vh[ridx]);
        }

        float* ob = out + (size_t)e0 * EMB + lane;
        if (full) {
            #pragma unroll
            for (int i = 0; i < 8; i++) {
                float o = fmaf(av[i], vf[i], uf[i]);
                asm volatile("st.global.cs.f32 [%0], %1;"
                             :: "l"(ob + i * EMB), "f"(o) : "memory");
            }
        } else {
            #pragma unroll
            for (int i = 0; i < 8; i++) {
                if (e0 + i < E) {
                    float o = fmaf(av[i], vf[i], uf[i]);
                    asm volatile("st.global.cs.f32 [%0], %1;"
                                 :: "l"(ob + i * EMB), "f"(o) : "memory");
                }
            }
        }
    }
}

// ---------------------------------------------------------------------------
extern "C" void kernel_launch(void* const* d_in, const int* in_sizes, int n_in,
                              void* d_out, int out_size)
{
    const float* edge_attr  = (const float*)d_in[0];
    const int*   edge_index = (const int*)d_in[1];   // [2, E] int32; row 0 = src
    const float* w_v2h = (const float*)d_in[3];
    const float* b_v2h = (const float*)d_in[4];
    const float* w_t1  = (const float*)d_in[5];
    const float* b_t1  = (const float*)d_in[6];
    const float* w_t2  = (const float*)d_in[7];
    const float* b_t2  = (const float*)d_in[8];
    const float* w_u1  = (const float*)d_in[9];
    const float* b_u1  = (const float*)d_in[10];
    const float* w_u2  = (const float*)d_in[11];
    const float* b_u2  = (const float*)d_in[12];
    float*       out   = (float*)d_out;

    int E = in_sizes[0];
    int C = in_sizes[2];

    void* hist_ptr = nullptr;
    cudaGetSymbolAddress(&hist_ptr, d_hist);
    cudaMemsetAsync(hist_ptr, 0, (size_t)C * NB * sizeof(float2), 0);

    precompute_kernel<<<1, 1024, 0, 0>>>(w_v2h, b_v2h, w_t1, b_t1,
                                         w_t2, b_t2, w_u1, b_u1);

    int blocks = (E + 255) / 256;
    pass1_kernel<<<blocks, 256, 0, 0>>>(edge_attr, edge_index, E);

    int gblocks = (C + 7) / 8;
    gtable_kernel<<<gblocks, 256, 0, 0>>>(C);
    uvbuild_kernel<<<gblocks, 256, 0, 0>>>(w_u2, b_u2, C);

    pass2_kernel<<<1184, 256, 0, 0>>>(edge_attr, edge_index, out, E);
}

// round 10
// speedup vs baseline: 1.0814x; 1.0814x over previous
#include <cuda_runtime.h>
#include <cuda_fp16.h>
#include <cstdint>

#define MAXC 10016
#define EMB 32
#define NB 33   // buckets = 32 knees + 1

// Scratch (__device__ globals; no allocation allowed)
__device__ __align__(16) float2 d_hist[MAXC * NB];    // per (candidate,bucket): {sum a, count}
__device__ float d_p[EMB], d_q[EMB], d_p1[EMB];
__device__ float d_u[EMB];
__device__ __align__(16) float d_W[EMB * EMB];        // w_t2 @ w_u1_bot
__device__ float d_q1v[EMB];
__device__ float d_ts[64];                             // sorted global thresholds (+INF pad)
__device__ int   d_perm[EMB];
// Piecewise-linear output table: out = U + a*V per (candidate, bucket)
__device__ __align__(16) float2 d_UV[(size_t)MAXC * NB * EMB];   // 84.6 MB, L2-resident
__device__ __align__(16) __half d_kneeh[MAXC * EMB];             // fp16 knees (64B/row)

// ---------------------------------------------------------------------------
// Precompute folded weights + sorted global thresholds (tiny, 1 block)
// ---------------------------------------------------------------------------
__global__ void precompute_kernel(const float* __restrict__ w_v2h,
                                  const float* __restrict__ b_v2h,
                                  const float* __restrict__ w_t1,
                                  const float* __restrict__ b_t1,
                                  const float* __restrict__ w_t2,
                                  const float* __restrict__ b_t2,
                                  const float* __restrict__ w_u1,
                                  const float* __restrict__ b_u1)
{
    __shared__ float tarr[EMB];
    int tid = threadIdx.x;
    int m = tid >> 5, k = tid & 31;

    float w = 0.f;
    #pragma unroll
    for (int j = 0; j < EMB; j++)
        w += w_t2[m * EMB + j] * w_u1[(EMB + j) * EMB + k];
    d_W[m * EMB + k] = w;

    if (m == 0) {
        float u = 0.f;
        #pragma unroll
        for (int j = 0; j < EMB; j++)
            u += b_t2[j] * w_u1[(EMB + j) * EMB + k];
        d_u[k] = u;

        float p = 0.f, q = 0.f, p1 = 0.f, q1 = 0.f;
        #pragma unroll
        for (int i = 0; i < EMB; i++) {
            float v = w_v2h[i];
            float b = b_v2h[i];
            p  += v * w_t1[i * EMB + k];
            q  += b * w_t1[i * EMB + k];
            p1 += v * w_u1[i * EMB + k];
            q1 += b * w_u1[i * EMB + k];
        }
        float qe = q + b_t1[k];
        d_p[k]   = p;
        d_q[k]   = qe;
        d_p1[k]  = p1;
        d_q1v[k] = q1 + b_u1[k];
        float t = (p != 0.f) ? (-qe / p) : __int_as_float(0x7f800000);
        tarr[k] = t;
    }
    __syncthreads();

    if (tid < 32) {
        float t = tarr[tid];
        int r = 0;
        #pragma unroll
        for (int j = 0; j < 32; j++) {
            float tj = tarr[j];
            r += (tj < t) || (tj == t && j < tid);
        }
        d_ts[r] = t;
        d_perm[r] = tid;
    } else if (tid < 64) {
        d_ts[tid] = __int_as_float(0x7f800000);
    }
}

// ---------------------------------------------------------------------------
// Pass 1: per-edge bucket(a) via binary search, one red.v2 {a,1} per edge
// ---------------------------------------------------------------------------
__global__ __launch_bounds__(256) void pass1_kernel(
    const float* __restrict__ edge_attr,
    const int* __restrict__ src,
    int E)
{
    __shared__ float ts[64];
    if (threadIdx.x < 64) ts[threadIdx.x] = d_ts[threadIdx.x];
    __syncthreads();

    int e = blockIdx.x * blockDim.x + threadIdx.x;
    if (e >= E) return;

    float a = edge_attr[e];
    int c = src[e];

    int pos = 0;
    #pragma unroll
    for (int s = 32; s >= 1; s >>= 1)
        if (ts[pos + s - 1] < a) pos += s;

    float2* addr = d_hist + c * NB + pos;
    asm volatile("red.global.add.v2.f32 [%0], {%1, %2};"
                 :: "l"(addr), "f"(a), "f"(1.0f) : "memory");
}

// ---------------------------------------------------------------------------
// Fused G + UV build: warp per candidate.
//   1) shfl-scan hist -> sumR -> G[k] (registers/shared, no global G)
//   2) knees t_k = -G_k/p1_k (stored fp16), rank them
//   3) incremental U,V per bucket; UV stored packed float2
// ---------------------------------------------------------------------------
__global__ __launch_bounds__(256) void guv_kernel(
    const float* __restrict__ w_u2,
    const float* __restrict__ b_u2,
    int C)
{
    __shared__ float sW[EMB * EMB];      // w_t2 @ w_u1_bot
    __shared__ float sw2[EMB * EMB];     // w_u2[j][k]
    __shared__ float su[EMB], sq1[EMB], sp[EMB], sq[EMB], sp1[EMB], sb[EMB];
    __shared__ int   sperm[EMB];
    __shared__ float sR[8][EMB];         // sumR per warp
    __shared__ float st[8][EMB];         // knees per warp (f32 for exact ranking)
    __shared__ float sG[8][EMB];
    __shared__ int   sjb[8][EMB];        // rank -> feature

    for (int i = threadIdx.x; i < EMB * EMB; i += blockDim.x) {
        sW[i]  = d_W[i];
        sw2[i] = w_u2[i];
    }
    if (threadIdx.x < EMB) {
        su[threadIdx.x]  = d_u[threadIdx.x];
        sq1[threadIdx.x] = d_q1v[threadIdx.x];
        sp[threadIdx.x]  = d_p[threadIdx.x];
        sq[threadIdx.x]  = d_q[threadIdx.x];
        sp1[threadIdx.x] = d_p1[threadIdx.x];
        sb[threadIdx.x]  = b_u2[threadIdx.x];
        sperm[threadIdx.x] = d_perm[threadIdx.x];
    }
    __syncthreads();

    int lane = threadIdx.x & 31;
    int wid  = threadIdx.x >> 5;
    int c = blockIdx.x * 8 + wid;
    if (c >= C) return;

    // ---- stage 1: G ----
    float2 h   = d_hist[c * NB + lane];
    float2 h32 = d_hist[c * NB + 32];

    float Ps = h.x, Pn = h.y;
    #pragma unroll
    for (int d = 1; d < 32; d <<= 1) {
        float xs = __shfl_up_sync(0xffffffffu, Ps, d);
        float xn = __shfl_up_sync(0xffffffffu, Pn, d);
        if (lane >= d) { Ps += xs; Pn += xn; }
    }
    float Ts = __shfl_sync(0xffffffffu, Ps, 31) + h32.x;
    float Tn = __shfl_sync(0xffffffffu, Pn, 31) + h32.y;

    {
        int k = sperm[lane];
        float p = sp[k], q = sq[k];
        float sumR;
        if (p > 0.f)      sumR = p * (Ts - Ps) + q * (Tn - Pn);
        else if (p < 0.f) sumR = p * Ps + q * Pn;
        else              sumR = Tn * fmaxf(q, 0.f);
        sR[wid][k] = sumR;
    }
    __syncwarp();

    float Gk = sq1[lane] + Tn * su[lane];
    #pragma unroll
    for (int m = 0; m < EMB; m++)
        Gk = fmaf(sR[wid][m], sW[m * EMB + lane], Gk);

    // ---- stage 2: knees ----
    float p1k = sp1[lane];
    float t = (p1k != 0.f) ? (-Gk / p1k) : __int_as_float(0x7f800000);
    d_kneeh[c * EMB + lane] = __float2half_rn(t);   // overflow -> +-inf, OK

    st[wid][lane] = t;
    sG[wid][lane] = Gk;
    __syncwarp();

    int r = 0;
    #pragma unroll
    for (int j = 0; j < EMB; j++) {
        float tj = st[wid][j];
        r += (tj < t) || (tj == t && j < lane);
    }
    sjb[wid][r] = lane;
    __syncwarp();

    // ---- stage 3: UV ----
    // base: bucket 0 (a below all knees): active iff p1<0, or p1==0 && G>0
    float U = sb[lane];
    float V = 0.f;
    #pragma unroll
    for (int j = 0; j < EMB; j++) {
        float pj = sp1[j];
        float gj = sG[wid][j];
        bool act = (pj < 0.f) || (pj == 0.f && gj > 0.f);
        if (act) {
            U = fmaf(gj, sw2[j * EMB + lane], U);
            V = fmaf(pj, sw2[j * EMB + lane], V);
        }
    }

    float2* uvrow = d_UV + (size_t)c * NB * EMB;
    uvrow[lane] = make_float2(U, V);

    for (int b = 1; b < NB; b++) {
        int j = sjb[wid][b - 1];
        float pj = sp1[j];
        float s = (pj > 0.f) ? 1.f : ((pj < 0.f) ? -1.f : 0.f);
        float wjk = sw2[j * EMB + lane];
        U = fmaf(s * sG[wid][j], wjk, U);
        V = fmaf(s * pj, wjk, V);
        uvrow[b * EMB + lane] = make_float2(U, V);
    }
}

// ---------------------------------------------------------------------------
// Pass 2: warp handles 8 edges/iter. Per edge: fp16 knee row (64B) ->
// ballot -> bucket; packed UV row float2 (256B, one LDG.64 request);
// out = fma(a, V, U); streaming store.
// ---------------------------------------------------------------------------
__global__ __launch_bounds__(256) void pass2_kernel(
    const float* __restrict__ edge_attr,
    const int* __restrict__ src,
    float* __restrict__ out,
    int E)
{
    int lane = threadIdx.x & 31;
    int wid  = threadIdx.x >> 5;
    int gw   = blockIdx.x * 8 + wid;
    int nw   = gridDim.x * 8;

    int ngroups = (E + 7) >> 3;
    for (int g = gw; g < ngroups; g += nw) {
        int e0 = g * 8;
        float av[8];
        int   cv[8];
        bool full = (e0 + 8 <= E);
        if (full) {
            float4 aA = *(const float4*)(edge_attr + e0);
            float4 aB = *(const float4*)(edge_attr + e0 + 4);
            int4   cA = *(const int4*)(src + e0);
            int4   cB = *(const int4*)(src + e0 + 4);
            av[0]=aA.x; av[1]=aA.y; av[2]=aA.z; av[3]=aA.w;
            av[4]=aB.x; av[5]=aB.y; av[6]=aB.z; av[7]=aB.w;
            cv[0]=cA.x; cv[1]=cA.y; cv[2]=cA.z; cv[3]=cA.w;
            cv[4]=cB.x; cv[5]=cB.y; cv[6]=cB.z; cv[7]=cB.w;
        } else {
            #pragma unroll
            for (int i = 0; i < 8; i++) {
                int e = (e0 + i < E) ? (e0 + i) : (E - 1);
                av[i] = edge_attr[e];
                cv[i] = src[e];
            }
        }

        // fp16 knee rows (coalesced 64B each), MLP=8
        float tk[8];
        #pragma unroll
        for (int i = 0; i < 8; i++)
            tk[i] = __half2float(d_kneeh[cv[i] * EMB + lane]);

        int bk[8];
        #pragma unroll
        for (int i = 0; i < 8; i++)
            bk[i] = __popc(__ballot_sync(0xffffffffu, tk[i] < av[i]));

        // packed UV rows (coalesced 256B each, one request), MLP=8
        float2 uv[8];
        #pragma unroll
        for (int i = 0; i < 8; i++)
            uv[i] = d_UV[((size_t)cv[i] * NB + bk[i]) * EMB + lane];

        float* ob = out + (size_t)e0 * EMB + lane;
        if (full) {
            #pragma unroll
            for (int i = 0; i < 8; i++) {
                float o = fmaf(av[i], uv[i].y, uv[i].x);
                asm volatile("st.global.cs.f32 [%0], %1;"
                             :: "l"(ob + i * EMB), "f"(o) : "memory");
            }
        } else {
            #pragma unroll
            for (int i = 0; i < 8; i++) {
                if (e0 + i < E) {
                    float o = fmaf(av[i], uv[i].y, uv[i].x);
                    asm volatile("st.global.cs.f32 [%0], %1;"
                                 :: "l"(ob + i * EMB), "f"(o) : "memory");
                }
            }
        }
    }
}

// ---------------------------------------------------------------------------
extern "C" void kernel_launch(void* const* d_in, const int* in_sizes, int n_in,
                              void* d_out, int out_size)
{
    const float* edge_attr  = (const float*)d_in[0];
    const int*   edge_index = (const int*)d_in[1];   // [2, E] int32; row 0 = src
    const float* w_v2h = (const float*)d_in[3];
    const float* b_v2h = (const float*)d_in[4];
    const float* w_t1  = (const float*)d_in[5];
    const float* b_t1  = (const float*)d_in[6];
    const float* w_t2  = (const float*)d_in[7];
    const float* b_t2  = (const float*)d_in[8];
    const float* w_u1  = (const float*)d_in[9];
    const float* b_u1  = (const float*)d_in[10];
    const float* w_u2  = (const float*)d_in[11];
    const float* b_u2  = (const float*)d_in[12];
    float*       out   = (float*)d_out;

    int E = in_sizes[0];
    int C = in_sizes[2];

    void* hist_ptr = nullptr;
    cudaGetSymbolAddress(&hist_ptr, d_hist);
    cudaMemsetAsync(hist_ptr, 0, (size_t)C * NB * sizeof(float2), 0);

    precompute_kernel<<<1, 1024, 0, 0>>>(w_v2h, b_v2h, w_t1, b_t1,
                                         w_t2, b_t2, w_u1, b_u1);

    int blocks = (E + 255) / 256;
    pass1_kernel<<<blocks, 256, 0, 0>>>(edge_attr, edge_index, E);

    int gblocks = (C + 7) / 8;
    guv_kernel<<<gblocks, 256, 0, 0>>>(w_u2, b_u2, C);

    pass2_kernel<<<1184, 256, 0, 0>>>(edge_attr, edge_index, out, E);
}

// round 11
// speedup vs baseline: 1.2032x; 1.1127x over previous
#include <cuda_runtime.h>
#include <cuda_fp16.h>
#include <cstdint>

#define MAXC 10016
#define EMB 32
#define NB 33   // buckets = 32 knees + 1

// Scratch (__device__ globals; no allocation allowed)
__device__ __align__(16) float2 d_hist[MAXC * NB];    // per (candidate,bucket): {sum a, count}
__device__ float d_p[EMB], d_q[EMB], d_p1[EMB];
__device__ float d_u[EMB];
__device__ __align__(16) float d_W[EMB * EMB];        // w_t2 @ w_u1_bot
__device__ float d_q1v[EMB];
__device__ float d_ts[64];                             // sorted global thresholds (+INF pad)
__device__ int   d_perm[EMB];
// Piecewise-linear output table: out = U + a*V per (candidate, bucket)
__device__ __align__(16) float2 d_UV[(size_t)MAXC * NB * EMB];   // 84.6 MB, L2-resident
__device__ __align__(16) __half d_kneeh[MAXC * EMB];             // fp16 knees (64B/row)

// ---------------------------------------------------------------------------
// Precompute folded weights + sorted global thresholds (tiny, 1 block)
// ---------------------------------------------------------------------------
__global__ void precompute_kernel(const float* __restrict__ w_v2h,
                                  const float* __restrict__ b_v2h,
                                  const float* __restrict__ w_t1,
                                  const float* __restrict__ b_t1,
                                  const float* __restrict__ w_t2,
                                  const float* __restrict__ b_t2,
                                  const float* __restrict__ w_u1,
                                  const float* __restrict__ b_u1)
{
    __shared__ float tarr[EMB];
    int tid = threadIdx.x;
    int m = tid >> 5, k = tid & 31;

    float w = 0.f;
    #pragma unroll
    for (int j = 0; j < EMB; j++)
        w += w_t2[m * EMB + j] * w_u1[(EMB + j) * EMB + k];
    d_W[m * EMB + k] = w;

    if (m == 0) {
        float u = 0.f;
        #pragma unroll
        for (int j = 0; j < EMB; j++)
            u += b_t2[j] * w_u1[(EMB + j) * EMB + k];
        d_u[k] = u;

        float p = 0.f, q = 0.f, p1 = 0.f, q1 = 0.f;
        #pragma unroll
        for (int i = 0; i < EMB; i++) {
            float v = w_v2h[i];
            float b = b_v2h[i];
            p  += v * w_t1[i * EMB + k];
            q  += b * w_t1[i * EMB + k];
            p1 += v * w_u1[i * EMB + k];
            q1 += b * w_u1[i * EMB + k];
        }
        float qe = q + b_t1[k];
        d_p[k]   = p;
        d_q[k]   = qe;
        d_p1[k]  = p1;
        d_q1v[k] = q1 + b_u1[k];
        float t = (p != 0.f) ? (-qe / p) : __int_as_float(0x7f800000);
        tarr[k] = t;
    }
    __syncthreads();

    if (tid < 32) {
        float t = tarr[tid];
        int r = 0;
        #pragma unroll
        for (int j = 0; j < 32; j++) {
            float tj = tarr[j];
            r += (tj < t) || (tj == t && j < tid);
        }
        d_ts[r] = t;
        d_perm[r] = tid;
    } else if (tid < 64) {
        d_ts[tid] = __int_as_float(0x7f800000);
    }
}

// ---------------------------------------------------------------------------
// Pass 1: 4 edges/thread (float4/int4 loads), bucket via 6-step search,
// one red.v2 {a,1} per edge
// ---------------------------------------------------------------------------
__global__ __launch_bounds__(256) void pass1_kernel(
    const float* __restrict__ edge_attr,
    const int* __restrict__ src,
    int E)
{
    __shared__ float ts[64];
    if (threadIdx.x < 64) ts[threadIdx.x] = d_ts[threadIdx.x];
    __syncthreads();

    int base = (blockIdx.x * blockDim.x + threadIdx.x) * 4;
    if (base >= E) return;

    float a4[4];
    int   c4[4];
    if (base + 4 <= E) {
        float4 aa = *(const float4*)(edge_attr + base);
        int4   cc = *(const int4*)(src + base);
        a4[0]=aa.x; a4[1]=aa.y; a4[2]=aa.z; a4[3]=aa.w;
        c4[0]=cc.x; c4[1]=cc.y; c4[2]=cc.z; c4[3]=cc.w;
    } else {
        #pragma unroll
        for (int i = 0; i < 4; i++) {
            int e = (base + i < E) ? (base + i) : (E - 1);
            a4[i] = edge_attr[e];
            c4[i] = src[e];
        }
    }

    int n = (base + 4 <= E) ? 4 : (E - base);
    int pos[4];
    #pragma unroll
    for (int i = 0; i < 4; i++) {
        int p = 0;
        #pragma unroll
        for (int s = 32; s >= 1; s >>= 1)
            if (ts[p + s - 1] < a4[i]) p += s;
        pos[i] = p;
    }

    #pragma unroll
    for (int i = 0; i < 4; i++) {
        if (i < n) {
            float2* addr = d_hist + c4[i] * NB + pos[i];
            asm volatile("red.global.add.v2.f32 [%0], {%1, %2};"
                         :: "l"(addr), "f"(a4[i]), "f"(1.0f) : "memory");
        }
    }
}

// ---------------------------------------------------------------------------
// Fused G + UV build: warp per candidate.
// ---------------------------------------------------------------------------
__global__ __launch_bounds__(256) void guv_kernel(
    const float* __restrict__ w_u2,
    const float* __restrict__ b_u2,
    int C)
{
    __shared__ float sW[EMB * EMB];      // w_t2 @ w_u1_bot
    __shared__ float sw2[EMB * EMB];     // w_u2[j][k]
    __shared__ float su[EMB], sq1[EMB], sp[EMB], sq[EMB], sp1[EMB], sb[EMB];
    __shared__ int   sperm[EMB];
    __shared__ float sR[8][EMB];
    __shared__ float st[8][EMB];
    __shared__ float sG[8][EMB];
    __shared__ int   sjb[8][EMB];

    for (int i = threadIdx.x; i < EMB * EMB; i += blockDim.x) {
        sW[i]  = d_W[i];
        sw2[i] = w_u2[i];
    }
    if (threadIdx.x < EMB) {
        su[threadIdx.x]  = d_u[threadIdx.x];
        sq1[threadIdx.x] = d_q1v[threadIdx.x];
        sp[threadIdx.x]  = d_p[threadIdx.x];
        sq[threadIdx.x]  = d_q[threadIdx.x];
        sp1[threadIdx.x] = d_p1[threadIdx.x];
        sb[threadIdx.x]  = b_u2[threadIdx.x];
        sperm[threadIdx.x] = d_perm[threadIdx.x];
    }
    __syncthreads();

    int lane = threadIdx.x & 31;
    int wid  = threadIdx.x >> 5;
    int c = blockIdx.x * 8 + wid;
    if (c >= C) return;

    // ---- stage 1: G ----
    float2 h   = d_hist[c * NB + lane];
    float2 h32 = d_hist[c * NB + 32];

    float Ps = h.x, Pn = h.y;
    #pragma unroll
    for (int d = 1; d < 32; d <<= 1) {
        float xs = __shfl_up_sync(0xffffffffu, Ps, d);
        float xn = __shfl_up_sync(0xffffffffu, Pn, d);
        if (lane >= d) { Ps += xs; Pn += xn; }
    }
    float Ts = __shfl_sync(0xffffffffu, Ps, 31) + h32.x;
    float Tn = __shfl_sync(0xffffffffu, Pn, 31) + h32.y;

    {
        int k = sperm[lane];
        float p = sp[k], q = sq[k];
        float sumR;
        if (p > 0.f)      sumR = p * (Ts - Ps) + q * (Tn - Pn);
        else if (p < 0.f) sumR = p * Ps + q * Pn;
        else              sumR = Tn * fmaxf(q, 0.f);
        sR[wid][k] = sumR;
    }
    __syncwarp();

    float Gk = sq1[lane] + Tn * su[lane];
    #pragma unroll
    for (int m = 0; m < EMB; m++)
        Gk = fmaf(sR[wid][m], sW[m * EMB + lane], Gk);

    // ---- stage 2: knees ----
    float p1k = sp1[lane];
    float t = (p1k != 0.f) ? (-Gk / p1k) : __int_as_float(0x7f800000);
    d_kneeh[c * EMB + lane] = __float2half_rn(t);

    st[wid][lane] = t;
    sG[wid][lane] = Gk;
    __syncwarp();

    int r = 0;
    #pragma unroll
    for (int j = 0; j < EMB; j++) {
        float tj = st[wid][j];
        r += (tj < t) || (tj == t && j < lane);
    }
    sjb[wid][r] = lane;
    __syncwarp();

    // ---- stage 3: UV ----
    float U = sb[lane];
    float V = 0.f;
    #pragma unroll
    for (int j = 0; j < EMB; j++) {
        float pj = sp1[j];
        float gj = sG[wid][j];
        bool act = (pj < 0.f) || (pj == 0.f && gj > 0.f);
        if (act) {
            U = fmaf(gj, sw2[j * EMB + lane], U);
            V = fmaf(pj, sw2[j * EMB + lane], V);
        }
    }

    float2* uvrow = d_UV + (size_t)c * NB * EMB;
    uvrow[lane] = make_float2(U, V);

    for (int b = 1; b < NB; b++) {
        int j = sjb[wid][b - 1];
        float pj = sp1[j];
        float s = (pj > 0.f) ? 1.f : ((pj < 0.f) ? -1.f : 0.f);
        float wjk = sw2[j * EMB + lane];
        U = fmaf(s * sG[wid][j], wjk, U);
        V = fmaf(s * pj, wjk, V);
        uvrow[b * EMB + lane] = make_float2(U, V);
    }
}

// ---------------------------------------------------------------------------
// Pass 2: warp handles 16 edges/iter in phase-separated batches:
// 16 fp16 knee loads (MLP16) -> 16 ballots -> 16 packed UV loads (MLP16)
// -> 16 fma + streaming stores. Two L2 round-trips per 16 edges.
// ---------------------------------------------------------------------------
__global__ __launch_bounds__(256) void pass2_kernel(
    const float* __restrict__ edge_attr,
    const int* __restrict__ src,
    float* __restrict__ out,
    int E)
{
    int lane = threadIdx.x & 31;
    int wid  = threadIdx.x >> 5;
    int gw   = blockIdx.x * 8 + wid;
    int nw   = gridDim.x * 8;

    int ngroups = (E + 15) >> 4;
    for (int g = gw; g < ngroups; g += nw) {
        int e0 = g * 16;
        float av[16];
        int   cv[16];
        bool full = (e0 + 16 <= E);
        if (full) {
            #pragma unroll
            for (int v = 0; v < 4; v++) {
                float4 aa = *(const float4*)(edge_attr + e0 + v * 4);
                int4   cc = *(const int4*)(src + e0 + v * 4);
                av[v*4+0]=aa.x; av[v*4+1]=aa.y; av[v*4+2]=aa.z; av[v*4+3]=aa.w;
                cv[v*4+0]=cc.x; cv[v*4+1]=cc.y; cv[v*4+2]=cc.z; cv[v*4+3]=cc.w;
            }
        } else {
            #pragma unroll
            for (int i = 0; i < 16; i++) {
                int e = (e0 + i < E) ? (e0 + i) : (E - 1);
                av[i] = edge_attr[e];
                cv[i] = src[e];
            }
        }

        // phase 1: fp16 knee rows (64B each), MLP=16
        float tk[16];
        #pragma unroll
        for (int i = 0; i < 16; i++)
            tk[i] = __half2float(d_kneeh[cv[i] * EMB + lane]);

        // phase 2: warp-parallel bucket via ballot
        int bk[16];
        #pragma unroll
        for (int i = 0; i < 16; i++)
            bk[i] = __popc(__ballot_sync(0xffffffffu, tk[i] < av[i]));

        // phase 3: packed UV rows (256B each, one LDG.64 request), MLP=16
        float2 uv[16];
        #pragma unroll
        for (int i = 0; i < 16; i++)
            uv[i] = d_UV[((size_t)cv[i] * NB + bk[i]) * EMB + lane];

        // phase 4: fma + streaming stores
        float* ob = out + (size_t)e0 * EMB + lane;
        if (full) {
            #pragma unroll
            for (int i = 0; i < 16; i++) {
                float o = fmaf(av[i], uv[i].y, uv[i].x);
                asm volatile("st.global.cs.f32 [%0], %1;"
                             :: "l"(ob + i * EMB), "f"(o) : "memory");
            }
        } else {
            #pragma unroll
            for (int i = 0; i < 16; i++) {
                if (e0 + i < E) {
                    float o = fmaf(av[i], uv[i].y, uv[i].x);
                    asm volatile("st.global.cs.f32 [%0], %1;"
                                 :: "l"(ob + i * EMB), "f"(o) : "memory");
                }
            }
        }
    }
}

// ---------------------------------------------------------------------------
extern "C" void kernel_launch(void* const* d_in, const int* in_sizes, int n_in,
                              void* d_out, int out_size)
{
    const float* edge_attr  = (const float*)d_in[0];
    const int*   edge_index = (const int*)d_in[1];   // [2, E] int32; row 0 = src
    const float* w_v2h = (const float*)d_in[3];
    const float* b_v2h = (const float*)d_in[4];
    const float* w_t1  = (const float*)d_in[5];
    const float* b_t1  = (const float*)d_in[6];
    const float* w_t2  = (const float*)d_in[7];
    const float* b_t2  = (const float*)d_in[8];
    const float* w_u1  = (const float*)d_in[9];
    const float* b_u1  = (const float*)d_in[10];
    const float* w_u2  = (const float*)d_in[11];
    const float* b_u2  = (const float*)d_in[12];
    float*       out   = (float*)d_out;

    int E = in_sizes[0];
    int C = in_sizes[2];

    void* hist_ptr = nullptr;
    cudaGetSymbolAddress(&hist_ptr, d_hist);
    cudaMemsetAsync(hist_ptr, 0, (size_t)C * NB * sizeof(float2), 0);

    precompute_kernel<<<1, 1024, 0, 0>>>(w_v2h, b_v2h, w_t1, b_t1,
                                         w_t2, b_t2, w_u1, b_u1);

    int p1threads = (E + 3) / 4;
    int p1blocks = (p1threads + 255) / 256;
    pass1_kernel<<<p1blocks, 256, 0, 0>>>(edge_attr, edge_index, E);

    int gblocks = (C + 7) / 8;
    guv_kernel<<<gblocks, 256, 0, 0>>>(w_u2, b_u2, C);

    pass2_kernel<<<1184, 256, 0, 0>>>(edge_attr, edge_index, out, E);
}